// round 13
// baseline (speedup 1.0000x reference)
#include <cuda_runtime.h>
#include <math.h>

// Problem constants
#define B_      32
#define T_      1024
#define INCH    3
#define CD      12          // path channels: 1 time + 3 orig + 8 aug
#define SIGC    1884        // 12 + 144 + 1728
#define SIGPAD  1888        // padded shared stride
#define NBG     64          // B * G paths
#define CH_STEPS 32
#define NSTEPS  1023
#define DT_     (1.0f/1023.0f)
#define MIDS_PER_PATH 8     // 32 chunks / 4 per block

// Scratch (static device arrays — no allocation)
__device__ __align__(16) float g_mid[512 * SIGC];   // 8 per path, ~3.9 MB
__device__ __align__(16) float g_sig[NBG * SIGC];

typedef unsigned long long ull;

__device__ __forceinline__ ull pack2(float a, float b) {
    ull r;
    asm("mov.b64 %0, {%1,%2};" : "=l"(r) : "f"(a), "f"(b));
    return r;
}
__device__ __forceinline__ void ffma2(ull& d, ull a, ull b) {
    asm("fma.rn.f32x2 %0, %1, %2, %0;" : "+l"(d) : "l"(a), "l"(b));
}
union U64F2 { ull u; float2 f; };

// ---------------------------------------------------------------------------
// Kernel 1: 4 chunks (32 steps) per block, 72 threads per chunk
// (i = wt/6, j-pair j0=2m, j1=2m+1), software-pipelined mainloop:
// prefetch step t+1's d-row while issuing step t's FMA burst.
// Scalar s2/c3 (no packed copy/unpack — shorter dependency chain):
//   u   = di/6 + s1/2 ;  c3x = u*djx + s2x   (x = j0, j1)
//   S3[i][jx][:] += c3x * d[:]               (2 x 6 FFMA2)
//   v   = di/2 + s1   ;  s2x += v*djx ;  s1 += di
// Then fused level-1 Chen combine of the 4 chunks (threads 0..143).
// ---------------------------------------------------------------------------
__global__ __launch_bounds__(288) void sig_chunk4_kernel(
    const float* __restrict__ x, const float* __restrict__ aug_w)
{
    __shared__ __align__(16) float sh_d[4][(CH_STEPS + 1) * CD];  // +1 pad row
    __shared__ __align__(16) float sh_sig[4][SIGPAD];             // 30.2 KB
    __shared__ float sh_w[4][24];

    int tid = threadIdx.x;
    int sub = tid / 72;
    int wt  = tid - sub * 72;               // 0..71
    int g   = ((blockIdx.x * 4 + sub) >> 5) & 1;

    if (wt < 24) sh_w[sub][wt] = aug_w[g * 24 + wt];
    __syncthreads();

    // Fill increments: d[t] = [dt, dx0..2, W_g*dx]; rows past path end = 0.
    // tid<128 -> (sub2 = tid/32, step = tid%32); also zero the pad row.
    {
        int sub2 = tid >> 5;
        int st   = tid & 31;
        if (sub2 < 4) {
            int chunk2 = blockIdx.x * 4 + sub2;
            int bg2 = chunk2 >> 5;
            int c2  = chunk2 & 31;
            int b2  = bg2 >> 1;
            int t02 = c2 * CH_STEPS;
            float* dr = sh_d[sub2] + st * CD;
            if (t02 + st < NSTEPS) {
                const float* xp = x + ((size_t)b2 * T_ + (t02 + st)) * INCH;
                float dx0 = xp[3] - xp[0];
                float dx1 = xp[4] - xp[1];
                float dx2 = xp[5] - xp[2];
                dr[0] = DT_; dr[1] = dx0; dr[2] = dx1; dr[3] = dx2;
                const float* w = sh_w[sub2];
#pragma unroll
                for (int e = 0; e < 8; e++)
                    dr[4 + e] = w[e*3]*dx0 + w[e*3+1]*dx1 + w[e*3+2]*dx2;
            } else {
#pragma unroll
                for (int e = 0; e < CD; e++) dr[e] = 0.f;
            }
            if (st == 0) {   // zero the pad row (prefetch target at t=31)
                float* pr = sh_d[sub2] + CH_STEPS * CD;
#pragma unroll
                for (int e = 0; e < CD; e++) pr[e] = 0.f;
            }
        }
    }
    __syncthreads();

    int i = wt / 6;
    int m = wt - i * 6;

    float s1 = 0.f, s20 = 0.f, s21 = 0.f;
    ull s3a[6], s3b[6];
#pragma unroll
    for (int q = 0; q < 6; q++) { s3a[q] = 0ull; s3b[q] = 0ull; }

    const float* drbase = sh_d[sub];

    // prologue: load step 0
    ulonglong2 qa = ((const ulonglong2*)drbase)[0];
    ulonglong2 qb = ((const ulonglong2*)drbase)[1];
    ulonglong2 qc = ((const ulonglong2*)drbase)[2];
    float  di = drbase[i];
    float2 dj = *(const float2*)(drbase + 2 * m);

#pragma unroll 4
    for (int t = 0; t < CH_STEPS; t++) {
        // prefetch step t+1 (pad row at t=31; values unused after rotation)
        const float* nr = drbase + (t + 1) * CD;
        ulonglong2 nqa = ((const ulonglong2*)nr)[0];
        ulonglong2 nqb = ((const ulonglong2*)nr)[1];
        ulonglong2 nqc = ((const ulonglong2*)nr)[2];
        float  ndi = nr[i];
        float2 ndj = *(const float2*)(nr + 2 * m);

        // compute with step t values
        float u   = fmaf(di, (1.f/6.f), 0.5f * s1);
        float c30 = fmaf(u, dj.x, s20);
        float c31 = fmaf(u, dj.y, s21);
        ull cc0 = pack2(c30, c30);
        ull cc1 = pack2(c31, c31);

        ffma2(s3a[0], cc0, qa.x); ffma2(s3a[1], cc0, qa.y);
        ffma2(s3a[2], cc0, qb.x); ffma2(s3a[3], cc0, qb.y);
        ffma2(s3a[4], cc0, qc.x); ffma2(s3a[5], cc0, qc.y);
        ffma2(s3b[0], cc1, qa.x); ffma2(s3b[1], cc1, qa.y);
        ffma2(s3b[2], cc1, qb.x); ffma2(s3b[3], cc1, qb.y);
        ffma2(s3b[4], cc1, qc.x); ffma2(s3b[5], cc1, qc.y);

        float v = fmaf(di, 0.5f, s1);
        s20 = fmaf(v, dj.x, s20);
        s21 = fmaf(v, dj.y, s21);
        s1 += di;

        // rotate
        qa = nqa; qb = nqb; qc = nqc; di = ndi; dj = ndj;
    }

    // Store chunk signature into shared staging (signatory layout)
    {
        float* out = sh_sig[sub];
        if (m == 0) out[i] = s1;
        out[12 + i*12 + 2*m]     = s20;
        out[12 + i*12 + 2*m + 1] = s21;
        float* o3 = out + 156 + (i*12 + 2*m) * 12;   // row j0, then row j1
        U64F2 w0, w1, w2, w3, w4, w5;
        w0.u = s3a[0]; w1.u = s3a[1]; w2.u = s3a[2];
        w3.u = s3a[3]; w4.u = s3a[4]; w5.u = s3a[5];
        *(float4*)(o3)     = make_float4(w0.f.x, w0.f.y, w1.f.x, w1.f.y);
        *(float4*)(o3 + 4) = make_float4(w2.f.x, w2.f.y, w3.f.x, w3.f.y);
        *(float4*)(o3 + 8) = make_float4(w4.f.x, w4.f.y, w5.f.x, w5.f.y);
        w0.u = s3b[0]; w1.u = s3b[1]; w2.u = s3b[2];
        w3.u = s3b[3]; w4.u = s3b[4]; w5.u = s3b[5];
        *(float4*)(o3 + 12) = make_float4(w0.f.x, w0.f.y, w1.f.x, w1.f.y);
        *(float4*)(o3 + 16) = make_float4(w2.f.x, w2.f.y, w3.f.x, w3.f.y);
        *(float4*)(o3 + 20) = make_float4(w4.f.x, w4.f.y, w5.f.x, w5.f.y);
    }
    __syncthreads();

    // Fused level-1 Chen combine (4 chunks -> 1), threads 0..143
    if (tid < 144) {
        int ci = tid / 12;
        int cj = tid - ci * 12;

        float a1 = sh_sig[0][ci];
        float a2 = sh_sig[0][12 + tid];
        float a3[12];
        {
            const float* p = sh_sig[0] + 156 + tid * 12;
            float4 v0 = *(const float4*)p;
            float4 v1 = *(const float4*)(p + 4);
            float4 v2 = *(const float4*)(p + 8);
            a3[0]=v0.x; a3[1]=v0.y; a3[2]=v0.z;  a3[3]=v0.w;
            a3[4]=v1.x; a3[5]=v1.y; a3[6]=v1.z;  a3[7]=v1.w;
            a3[8]=v2.x; a3[9]=v2.y; a3[10]=v2.z; a3[11]=v2.w;
        }

#pragma unroll
        for (int cc = 1; cc < 4; cc++) {
            const float* Bp = sh_sig[cc];
            float4 b1a = *(const float4*)(Bp);
            float4 b1b = *(const float4*)(Bp + 4);
            float4 b1c = *(const float4*)(Bp + 8);
            float b1i = Bp[ci];
            float b1j = Bp[cj];
            float b2s = Bp[12 + tid];
            const float* r2 = Bp + 12 + cj * 12;
            float4 r2a = *(const float4*)(r2);
            float4 r2b = *(const float4*)(r2 + 4);
            float4 r2c = *(const float4*)(r2 + 8);
            const float* p3 = Bp + 156 + tid * 12;
            float4 b3a = *(const float4*)(p3);
            float4 b3b = *(const float4*)(p3 + 4);
            float4 b3c = *(const float4*)(p3 + 8);

            a3[0]  += b3a.x + a1*r2a.x + a2*b1a.x;
            a3[1]  += b3a.y + a1*r2a.y + a2*b1a.y;
            a3[2]  += b3a.z + a1*r2a.z + a2*b1a.z;
            a3[3]  += b3a.w + a1*r2a.w + a2*b1a.w;
            a3[4]  += b3b.x + a1*r2b.x + a2*b1b.x;
            a3[5]  += b3b.y + a1*r2b.y + a2*b1b.y;
            a3[6]  += b3b.z + a1*r2b.z + a2*b1b.z;
            a3[7]  += b3b.w + a1*r2b.w + a2*b1b.w;
            a3[8]  += b3c.x + a1*r2c.x + a2*b1c.x;
            a3[9]  += b3c.y + a1*r2c.y + a2*b1c.y;
            a3[10] += b3c.z + a1*r2c.z + a2*b1c.z;
            a3[11] += b3c.w + a1*r2c.w + a2*b1c.w;
            a2 += b2s + a1 * b1j;     // uses OLD a1
            a1 += b1i;
        }

        float* out = g_mid + (size_t)blockIdx.x * SIGC;
        if (cj == 0) out[ci] = a1;
        out[12 + tid] = a2;
        float* o3 = out + 156 + tid * 12;
        *(float4*)(o3)     = make_float4(a3[0], a3[1], a3[2], a3[3]);
        *(float4*)(o3 + 4) = make_float4(a3[4], a3[5], a3[6], a3[7]);
        *(float4*)(o3 + 8) = make_float4(a3[8], a3[9], a3[10], a3[11]);
    }
}

// ---------------------------------------------------------------------------
// Kernel 2: level-2 Chen combine (8 mids -> final signature per path)
// ---------------------------------------------------------------------------
__global__ __launch_bounds__(160) void sig_combine2_kernel()
{
    int tid = threadIdx.x;
    if (tid >= 144) return;
    int i = tid / 12;
    int j = tid - i * 12;

    const float* base = g_mid + (size_t)blockIdx.x * MIDS_PER_PATH * SIGC;

    float a1 = base[i];
    float a2 = base[12 + tid];
    float a3[12];
    {
        const float* p = base + 156 + tid * 12;
        float4 v0 = *(const float4*)p;
        float4 v1 = *(const float4*)(p + 4);
        float4 v2 = *(const float4*)(p + 8);
        a3[0]=v0.x; a3[1]=v0.y; a3[2]=v0.z;  a3[3]=v0.w;
        a3[4]=v1.x; a3[5]=v1.y; a3[6]=v1.z;  a3[7]=v1.w;
        a3[8]=v2.x; a3[9]=v2.y; a3[10]=v2.z; a3[11]=v2.w;
    }

#pragma unroll
    for (int c = 1; c < MIDS_PER_PATH; c++) {
        const float* Bp = base + (size_t)c * SIGC;
        float4 b1a = *(const float4*)(Bp);
        float4 b1b = *(const float4*)(Bp + 4);
        float4 b1c = *(const float4*)(Bp + 8);
        float b1i = Bp[i];
        float b1j = Bp[j];
        float b2s = Bp[12 + tid];
        const float* r2 = Bp + 12 + j * 12;
        float4 r2a = *(const float4*)(r2);
        float4 r2b = *(const float4*)(r2 + 4);
        float4 r2c = *(const float4*)(r2 + 8);
        const float* p3 = Bp + 156 + tid * 12;
        float4 b3a = *(const float4*)(p3);
        float4 b3b = *(const float4*)(p3 + 4);
        float4 b3c = *(const float4*)(p3 + 8);

        a3[0]  += b3a.x + a1*r2a.x + a2*b1a.x;
        a3[1]  += b3a.y + a1*r2a.y + a2*b1a.y;
        a3[2]  += b3a.z + a1*r2a.z + a2*b1a.z;
        a3[3]  += b3a.w + a1*r2a.w + a2*b1a.w;
        a3[4]  += b3b.x + a1*r2b.x + a2*b1b.x;
        a3[5]  += b3b.y + a1*r2b.y + a2*b1b.y;
        a3[6]  += b3b.z + a1*r2b.z + a2*b1b.z;
        a3[7]  += b3b.w + a1*r2b.w + a2*b1b.w;
        a3[8]  += b3c.x + a1*r2c.x + a2*b1c.x;
        a3[9]  += b3c.y + a1*r2c.y + a2*b1c.y;
        a3[10] += b3c.z + a1*r2c.z + a2*b1c.z;
        a3[11] += b3c.w + a1*r2c.w + a2*b1c.w;
        a2 += b2s + a1 * b1j;
        a1 += b1i;
    }

    float* out = g_sig + (size_t)blockIdx.x * SIGC;
    if (j == 0) out[i] = a1;
    out[12 + tid] = a2;
    float* o3 = out + 156 + tid * 12;
    *(float4*)(o3)     = make_float4(a3[0], a3[1], a3[2], a3[3]);
    *(float4*)(o3 + 4) = make_float4(a3[4], a3[5], a3[6], a3[7]);
    *(float4*)(o3 + 8) = make_float4(a3[8], a3[9], a3[10], a3[11]);
}

// ---------------------------------------------------------------------------
// Kernel 3: one block per output element (b,o):
//   out[b][o] = sigmoid( sig[b] . lin_w[o] + lin_b[o] )
// ---------------------------------------------------------------------------
#define SIG2  (2 * SIGC)        // 3768
#define SIG2V (SIG2 / 4)        // 942 float4s

__global__ __launch_bounds__(128) void sig_out_kernel(
    const float* __restrict__ lin_w, const float* __restrict__ lin_b,
    float* __restrict__ out)
{
    int b = blockIdx.x >> 5;
    int o = blockIdx.x & 31;
    int tid = threadIdx.x;

    const float4* wr = (const float4*)(lin_w + (size_t)o * SIG2);
    const float4* sg = (const float4*)(g_sig + (size_t)b * SIG2);

    float acc = 0.f;
#pragma unroll
    for (int it = 0; it < 8; it++) {
        int m = tid + it * 128;
        if (m < SIG2V) {
            float4 w = __ldg(wr + m);
            float4 s = __ldg(sg + m);
            acc = fmaf(w.x, s.x, acc);
            acc = fmaf(w.y, s.y, acc);
            acc = fmaf(w.z, s.z, acc);
            acc = fmaf(w.w, s.w, acc);
        }
    }

#pragma unroll
    for (int off = 16; off; off >>= 1)
        acc += __shfl_down_sync(0xffffffffu, acc, off);

    __shared__ float sh[4];
    int warp = tid >> 5;
    int lane = tid & 31;
    if (lane == 0) sh[warp] = acc;
    __syncthreads();

    if (tid == 0) {
        float z = sh[0] + sh[1] + sh[2] + sh[3] + lin_b[o];
        out[b * 32 + o] = 1.0f / (1.0f + expf(-z));
    }
}

// ---------------------------------------------------------------------------
extern "C" void kernel_launch(void* const* d_in, const int* in_sizes, int n_in,
                              void* d_out, int out_size)
{
    const float* x     = (const float*)d_in[0];  // (32,1024,3)
    const float* aug_w = (const float*)d_in[1];  // (2,8,3)
    // d_in[2] = aug_b — unused (bias cancels in path increments)
    const float* lin_w = (const float*)d_in[3];  // (32, 3768)
    const float* lin_b = (const float*)d_in[4];  // (32,)
    float* out = (float*)d_out;                  // (32,32)

    sig_chunk4_kernel<<<512, 288>>>(x, aug_w);
    sig_combine2_kernel<<<NBG, 160>>>();
    sig_out_kernel<<<B_ * 32, 128>>>(lin_w, lin_b, out);
}